// round 5
// baseline (speedup 1.0000x reference)
#include <cuda_runtime.h>
#include <cstdint>

#define BATCH 4096
#define INF   1024
#define OUTF  1024
#define NL    16

#define BM 128
#define BN 256
#define BK 32                  // kcat per chunk = 2 i-values x 16 leaves
#define NIT (INF/2)            // 512 pw chunks
#define NTOT (NIT+1)           // +1 bias tile
#define KCAT (INF*NL)

// smem layout (floats)
#define A_BUF_F   4096         // 8 mtiles x 4 ksteps x 32 lanes x 4
#define NA_BUF    3
#define B_PITCH   36           // floats per B row (144B, conflict-free)
#define B_BUF_F   (BN*B_PITCH) // 9216
#define NB_BUF    4
#define A_OFF_F   0
#define B_OFF_F   (NA_BUF*A_BUF_F)             // 12288
#define GS_OFF_F  (B_OFF_F + NB_BUF*B_BUF_F)   // 49152
#define GS_PITCH  20
#define SMEM_F    (GS_OFF_F + BM*GS_PITCH)     // 51712 floats
#define SMEM_B_TOTAL (SMEM_F*4)                // 206848 bytes

// device scratch (allocation-free)
__device__ float g_gate[BATCH * NL];
__device__ float g_xT[INF * BATCH];            // x transposed [i][b]

__device__ __forceinline__ uint32_t smem_u32_of(const void* p) {
    uint32_t a;
    asm("{ .reg .u64 t; cvta.to.shared.u64 t, %1; cvt.u32.u64 %0, t; }" : "=r"(a) : "l"(p));
    return a;
}
__device__ __forceinline__ uint32_t tf32r(float f) {
    uint32_t u;
    asm("cvt.rna.tf32.f32 %0, %1;" : "=r"(u) : "f"(f));
    return u;
}
__device__ __forceinline__ void cp_async16(uint32_t sa, const void* ga) {
    asm volatile("cp.async.cg.shared.global [%0], [%1], 16;" :: "r"(sa), "l"(ga));
}
__device__ __forceinline__ void mma_tf32(float* c, const uint32_t* a, uint32_t b0, uint32_t b1) {
    asm volatile(
        "mma.sync.aligned.m16n8k8.row.col.f32.tf32.tf32.f32 "
        "{%0,%1,%2,%3}, {%4,%5,%6,%7}, {%8,%9}, {%0,%1,%2,%3};"
        : "+f"(c[0]), "+f"(c[1]), "+f"(c[2]), "+f"(c[3])
        : "r"(a[0]), "r"(a[1]), "r"(a[2]), "r"(a[3]), "r"(b0), "r"(b1));
}

// ---------------------------------------------------------------------------
// x transpose: g_xT[i][b] = x[b][i]
// ---------------------------------------------------------------------------
__global__ __launch_bounds__(256)
void transpose_x_kernel(const float* __restrict__ x) {
    __shared__ float t[32][33];
    int i0 = blockIdx.x * 32, b0 = blockIdx.y * 32;
    int tx = threadIdx.x, ty = threadIdx.y;      // 32 x 8
    #pragma unroll
    for (int j = 0; j < 32; j += 8)
        t[ty + j][tx] = x[(size_t)(b0 + ty + j) * INF + i0 + tx];
    __syncthreads();
    #pragma unroll
    for (int j = 0; j < 32; j += 8)
        g_xT[(size_t)(i0 + ty + j) * BATCH + b0 + tx] = t[tx][ty + j];
}

// ---------------------------------------------------------------------------
// gating: g = softmax(x @ gw + gb). Warp per row, gw cached in smem.
// ---------------------------------------------------------------------------
__global__ __launch_bounds__(256)
void gating_kernel(const float* __restrict__ x,
                   const float* __restrict__ gw,
                   const float* __restrict__ gb) {
    extern __shared__ float gw_s[];   // [1024][17]
    int tid = threadIdx.x, warp = tid >> 5, lane = tid & 31;

    for (int idx = tid; idx < INF * NL; idx += 256) {
        int i = idx >> 4, l = idx & 15;
        gw_s[i * 17 + l] = gw[idx];
    }
    __syncthreads();

    int row = blockIdx.x * 8 + warp;
    const float* xr = x + (size_t)row * INF;

    float acc[16];
    #pragma unroll
    for (int l = 0; l < 16; l++) acc[l] = 0.f;

    #pragma unroll 4
    for (int jj = 0; jj < 32; jj++) {
        int i = lane + 32 * jj;
        float xv = xr[i];
        const float* gr = gw_s + i * 17;
        #pragma unroll
        for (int l = 0; l < 16; l++) acc[l] = fmaf(xv, gr[l], acc[l]);
    }
    #pragma unroll
    for (int o = 16; o > 0; o >>= 1)
        #pragma unroll
        for (int l = 0; l < 16; l++)
            acc[l] += __shfl_xor_sync(0xffffffffu, acc[l], o);

    if (lane < 16) {
        float v[16], m = -1e30f;
        #pragma unroll
        for (int l = 0; l < 16; l++) { v[l] = acc[l] + gb[l]; m = fmaxf(m, v[l]); }
        float s = 0.f;
        #pragma unroll
        for (int l = 0; l < 16; l++) { v[l] = __expf(v[l] - m); s += v[l]; }
        g_gate[row * NL + lane] = v[lane] / s;
    }
}

// ---------------------------------------------------------------------------
// main GEMM: out = Y @ PW^T + g @ pb^T via mma.sync tf32 m16n8k8
// B operand: raw fp32 bits (HW-truncated tf32). A operand: cvt.rna.tf32.
// 4 B-buffers (prefetch distance 2), 3 A-buffers, x register-prefetched.
// ---------------------------------------------------------------------------
__global__ __launch_bounds__(256, 1)
void moe_mma_kernel(const float* __restrict__ pw,
                    const float* __restrict__ pb,
                    float* __restrict__ out) {
    extern __shared__ float sm[];
    const int tid  = threadIdx.x;
    const int warp = tid >> 5, lane = tid & 31;
    const int m_blk = blockIdx.y * BM;
    const int n_blk = blockIdx.x * BN;
    const int warpM = warp & 1, warpN = warp >> 1;

    // ---- load g tile into smem (pitch 20, conflict-free for generator) ----
    for (int idx = tid; idx < BM * NL; idx += 256) {
        int m = idx >> 4, l = idx & 15;
        sm[GS_OFF_F + m * GS_PITCH + l] = g_gate[(size_t)(m_blk + m) * NL + l];
    }

    // generator role: mtile = warp, fragment slot = lane
    const int q = lane >> 2, cc = lane & 3;
    const int gm0 = warp * 16 + q, gm1 = gm0 + 8;
    const float* gsr0 = sm + GS_OFF_F + gm0 * GS_PITCH;
    const float* gsr1 = sm + GS_OFF_F + gm1 * GS_PITCH;

    // B loader role
    const int f4 = tid & 7, rb = tid >> 3;

    auto loadB = [&](int c, int buf) {
        const float* src = pw + (size_t)n_blk * KCAT + (size_t)c * BK;
        uint32_t dst = smem_u32_of(sm + B_OFF_F + buf * B_BUF_F);
        #pragma unroll
        for (int qq = 0; qq < 8; qq++) {
            int row = rb + qq * 32;
            cp_async16(dst + (uint32_t)(row * B_PITCH + f4 * 4) * 4u,
                       src + (size_t)row * KCAT + f4 * 4);
        }
        asm volatile("cp.async.commit_group;" ::: "memory");
    };
    auto loadB_bias = [&](int buf) {
        int f4b = tid & 3, rbb = tid >> 2;
        uint32_t dst = smem_u32_of(sm + B_OFF_F + buf * B_BUF_F);
        #pragma unroll
        for (int qq = 0; qq < 4; qq++) {
            int row = rbb + qq * 64;
            cp_async16(dst + (uint32_t)(row * B_PITCH + f4b * 4) * 4u,
                       pb + (size_t)(n_blk + row) * NL + f4b * 4);
        }
        asm volatile("cp.async.commit_group;" ::: "memory");
    };
    auto fetchX = [&](int c) -> float4 {
        const float* xc0 = g_xT + (size_t)(2 * c) * BATCH + m_blk;
        return make_float4(__ldg(xc0 + gm0), __ldg(xc0 + gm1),
                           __ldg(xc0 + BATCH + gm0), __ldg(xc0 + BATCH + gm1));
    };
    auto genA = [&](int buf, float4 xv) {
        float x00 = xv.x, x01 = xv.y;   // i = 2c  rows gm0, gm1
        float x10 = xv.z, x11 = xv.w;   // i = 2c+1
        float ga0 = gsr0[cc],      gb0 = gsr1[cc];
        float ga1 = gsr0[cc + 4],  gb1 = gsr1[cc + 4];
        float ga2 = gsr0[cc + 8],  gb2 = gsr1[cc + 8];
        float ga3 = gsr0[cc + 12], gb3 = gsr1[cc + 12];
        uint4* dst = (uint4*)(sm + A_OFF_F + (size_t)(buf * 8 + warp) * 4 * 128) + lane;
        dst[0]  = make_uint4(tf32r(x00*ga0), tf32r(x01*gb0), tf32r(x00*ga1), tf32r(x01*gb1));
        dst[32] = make_uint4(tf32r(x00*ga2), tf32r(x01*gb2), tf32r(x00*ga3), tf32r(x01*gb3));
        dst[64] = make_uint4(tf32r(x10*ga0), tf32r(x11*gb0), tf32r(x10*ga1), tf32r(x11*gb1));
        dst[96] = make_uint4(tf32r(x10*ga2), tf32r(x11*gb2), tf32r(x10*ga3), tf32r(x11*gb3));
    };
    auto genA_bias = [&](int buf) {
        float ga0 = gsr0[cc],      gb0 = gsr1[cc];
        float ga1 = gsr0[cc + 4],  gb1 = gsr1[cc + 4];
        float ga2 = gsr0[cc + 8],  gb2 = gsr1[cc + 8];
        float ga3 = gsr0[cc + 12], gb3 = gsr1[cc + 12];
        uint4* dst = (uint4*)(sm + A_OFF_F + (size_t)(buf * 8 + warp) * 4 * 128) + lane;
        dst[0]  = make_uint4(tf32r(ga0), tf32r(gb0), tf32r(ga1), tf32r(gb1));
        dst[32] = make_uint4(tf32r(ga2), tf32r(gb2), tf32r(ga3), tf32r(gb3));
    };

    float acc[4][8][4];
    #pragma unroll
    for (int mt = 0; mt < 4; mt++)
        #pragma unroll
        for (int nt = 0; nt < 8; nt++)
            #pragma unroll
            for (int j = 0; j < 4; j++) acc[mt][nt][j] = 0.f;

    const float* Abase = sm + A_OFF_F;
    const float* Bbase = sm + B_OFF_F;
    const int bq = lane >> 2, bc = lane & 3;

    auto compute = [&](int bufB, int bufA, int nks) {
        const float* Ab = Abase + (size_t)bufA * A_BUF_F + (size_t)(warpM * 4) * 4 * 128;
        const float* Bb = Bbase + (size_t)bufB * B_BUF_F + (size_t)(warpN * 64 + bq) * B_PITCH;
        for (int ks = 0; ks < nks; ks++) {
            uint32_t a[4][4];
            #pragma unroll
            for (int mt = 0; mt < 4; mt++) {
                uint4 v = *(const uint4*)(Ab + (size_t)(mt * 4 + ks) * 128 + lane * 4);
                a[mt][0] = v.x; a[mt][1] = v.y; a[mt][2] = v.z; a[mt][3] = v.w;
            }
            uint32_t b[8][2];
            #pragma unroll
            for (int nt = 0; nt < 8; nt++) {
                const float* bp = Bb + nt * 8 * B_PITCH + ks * 8 + bc;
                b[nt][0] = __float_as_uint(bp[0]);
                b[nt][1] = __float_as_uint(bp[4]);
            }
            #pragma unroll
            for (int mt = 0; mt < 4; mt++)
                #pragma unroll
                for (int nt = 0; nt < 8; nt++)
                    mma_tf32(acc[mt][nt], a[mt], b[nt][0], b[nt][1]);
        }
    };

    // ---- prologue: 2 B chunks in flight, x prefetched, A chunk 0 genned ----
    loadB(0, 0);                      // group for chunk 0
    loadB(1, 1);                      // group for chunk 1
    float4 xv = fetchX(0);
    __syncthreads();                  // gs visible
    genA(0, xv);
    xv = fetchX(1);

    // ---- main loop: prefetch distance 2, one barrier per iteration ----
    #pragma unroll 1
    for (int it = 0; it < NTOT; it++) {
        const int lc = it + 2;        // loadB target chunk
        const int nc = it + 1;        // genA target chunk
        if (lc < NIT)       loadB(lc, lc & 3);
        else if (lc == NIT) loadB_bias(lc & 3);
        else asm volatile("cp.async.commit_group;" ::: "memory");  // empty group

        if (nc < NIT) {
            float4 xn;
            if (nc + 1 < NIT) xn = fetchX(nc + 1);
            genA(nc % NA_BUF, xv);
            xv = xn;
        } else if (nc == NIT) {
            genA_bias(nc % NA_BUF);
        }

        asm volatile("cp.async.wait_group 2;" ::: "memory");  // chunk it landed
        __syncthreads();
        compute(it & 3, it % NA_BUF, (it == NIT) ? 2 : 4);
    }

    // ---- epilogue: fragment store, 8B quad-coalesced ----
    #pragma unroll
    for (int mt = 0; mt < 4; mt++) {
        int m0 = m_blk + warpM * 64 + mt * 16 + (lane >> 2);
        #pragma unroll
        for (int nt = 0; nt < 8; nt++) {
            int n = n_blk + warpN * 64 + nt * 8 + 2 * (lane & 3);
            *(float2*)(out + (size_t)m0 * OUTF + n)       = make_float2(acc[mt][nt][0], acc[mt][nt][1]);
            *(float2*)(out + (size_t)(m0 + 8) * OUTF + n) = make_float2(acc[mt][nt][2], acc[mt][nt][3]);
        }
    }
}

// ---------------------------------------------------------------------------
extern "C" void kernel_launch(void* const* d_in, const int* in_sizes, int n_in,
                              void* d_out, int out_size) {
    const float* x  = (const float*)d_in[0];
    const float* gw = (const float*)d_in[1];
    const float* gb = (const float*)d_in[2];
    const float* pw = (const float*)d_in[3];
    const float* pb = (const float*)d_in[4];
    float* out = (float*)d_out;

    cudaFuncSetAttribute(gating_kernel, cudaFuncAttributeMaxDynamicSharedMemorySize,
                         INF * 17 * 4);
    cudaFuncSetAttribute(moe_mma_kernel, cudaFuncAttributeMaxDynamicSharedMemorySize,
                         SMEM_B_TOTAL);

    gating_kernel<<<BATCH / 8, 256, INF * 17 * 4>>>(x, gw, gb);
    transpose_x_kernel<<<dim3(INF / 32, BATCH / 32), dim3(32, 8)>>>(x);

    dim3 grid(OUTF / BN, BATCH / BM);   // (4, 32) = 128 CTAs, single wave
    moe_mma_kernel<<<grid, 256, SMEM_B_TOTAL>>>(pw, pb, out);
}

// round 6
// speedup vs baseline: 2.0344x; 2.0344x over previous
#include <cuda_runtime.h>
#include <cuda_fp16.h>
#include <cstdint>

#define BATCH 4096
#define INF   1024
#define OUTF  1024
#define NL    16

#define BM 128
#define BN 256
#define BK 64                  // kcat per chunk = 4 i-values x 16 leaves
#define NIT (INF/4)            // 256 pw chunks
#define NTOT (NIT+1)           // +1 bias tile
#define KCAT (INF*NL)

// smem layout (bytes)
#define A_BUF_B   16384        // 8 mtiles x 4 ksteps x 32 lanes x 16B
#define B_PITCH_H 72           // halves per B row (144B = 9x16B, conflict-free)
#define B_BUF_B   (256*144)    // 36864
#define A_OFF     0
#define B_OFF     (3*A_BUF_B)              // 49152
#define GS_OFF    (B_OFF + 3*B_BUF_B)      // 159744
#define GS_PITCH  20
#define SMEM_TOTAL (GS_OFF + BM*GS_PITCH*4)  // 169984 bytes

// device scratch (allocation-free)
__device__ float  g_gate[BATCH * NL];
__device__ float  g_xT[INF * BATCH];          // x transposed [i][b]
__device__ __half g_pwh[(size_t)OUTF * KCAT]; // pw in fp16
__device__ __half g_pbh[OUTF * NL];           // pb in fp16

__device__ __forceinline__ uint32_t smem_u32_of(const void* p) {
    uint32_t a;
    asm("{ .reg .u64 t; cvta.to.shared.u64 t, %1; cvt.u32.u64 %0, t; }" : "=r"(a) : "l"(p));
    return a;
}
__device__ __forceinline__ uint32_t h2u(float lo, float hi) {
    __half2 h = __floats2half2_rn(lo, hi);
    return *(uint32_t*)&h;
}
__device__ __forceinline__ void cp_async16(uint32_t sa, const void* ga) {
    asm volatile("cp.async.cg.shared.global [%0], [%1], 16;" :: "r"(sa), "l"(ga));
}
__device__ __forceinline__ void mma_f16(float* c, const uint4& a, uint32_t b0, uint32_t b1) {
    asm volatile(
        "mma.sync.aligned.m16n8k16.row.col.f32.f16.f16.f32 "
        "{%0,%1,%2,%3}, {%4,%5,%6,%7}, {%8,%9}, {%0,%1,%2,%3};"
        : "+f"(c[0]), "+f"(c[1]), "+f"(c[2]), "+f"(c[3])
        : "r"(a.x), "r"(a.y), "r"(a.z), "r"(a.w), "r"(b0), "r"(b1));
}

// ---------------------------------------------------------------------------
// x transpose: g_xT[i][b] = x[b][i]
// ---------------------------------------------------------------------------
__global__ __launch_bounds__(256)
void transpose_x_kernel(const float* __restrict__ x) {
    __shared__ float t[32][33];
    int i0 = blockIdx.x * 32, b0 = blockIdx.y * 32;
    int tx = threadIdx.x, ty = threadIdx.y;      // 32 x 8
    #pragma unroll
    for (int j = 0; j < 32; j += 8)
        t[ty + j][tx] = x[(size_t)(b0 + ty + j) * INF + i0 + tx];
    __syncthreads();
    #pragma unroll
    for (int j = 0; j < 32; j += 8)
        g_xT[(size_t)(i0 + ty + j) * BATCH + b0 + tx] = t[tx][ty + j];
}

// ---------------------------------------------------------------------------
// pw -> fp16 ; pb -> fp16
// ---------------------------------------------------------------------------
__global__ __launch_bounds__(256)
void conv_pw_kernel(const float* __restrict__ pw) {
    size_t idx = (size_t)blockIdx.x * 256 + threadIdx.x;   // 8 floats per thread
    float4 v0 = ((const float4*)pw)[idx * 2];
    float4 v1 = ((const float4*)pw)[idx * 2 + 1];
    uint4 o;
    o.x = h2u(v0.x, v0.y); o.y = h2u(v0.z, v0.w);
    o.z = h2u(v1.x, v1.y); o.w = h2u(v1.z, v1.w);
    ((uint4*)g_pwh)[idx] = o;
}
__global__ __launch_bounds__(256)
void conv_pb_kernel(const float* __restrict__ pb) {
    size_t idx = (size_t)blockIdx.x * 256 + threadIdx.x;
    float4 v0 = ((const float4*)pb)[idx * 2];
    float4 v1 = ((const float4*)pb)[idx * 2 + 1];
    uint4 o;
    o.x = h2u(v0.x, v0.y); o.y = h2u(v0.z, v0.w);
    o.z = h2u(v1.x, v1.y); o.w = h2u(v1.z, v1.w);
    ((uint4*)g_pbh)[idx] = o;
}

// ---------------------------------------------------------------------------
// gating: g = softmax(x @ gw + gb). 128 blocks, 4 rows per warp (amortize gw).
// ---------------------------------------------------------------------------
__global__ __launch_bounds__(256)
void gating_kernel(const float* __restrict__ x,
                   const float* __restrict__ gw,
                   const float* __restrict__ gb) {
    extern __shared__ float gw_s[];   // [1024][17]
    int tid = threadIdx.x, warp = tid >> 5, lane = tid & 31;

    for (int idx = tid; idx < INF * NL; idx += 256) {
        int i = idx >> 4, l = idx & 15;
        gw_s[i * 17 + l] = gw[idx];
    }
    __syncthreads();

    #pragma unroll 1
    for (int r = 0; r < 4; r++) {
        int row = blockIdx.x * 32 + warp * 4 + r;
        const float* xr = x + (size_t)row * INF;

        float acc[16];
        #pragma unroll
        for (int l = 0; l < 16; l++) acc[l] = 0.f;

        #pragma unroll 4
        for (int jj = 0; jj < 32; jj++) {
            int i = lane + 32 * jj;
            float xv = xr[i];
            const float* gr = gw_s + i * 17;
            #pragma unroll
            for (int l = 0; l < 16; l++) acc[l] = fmaf(xv, gr[l], acc[l]);
        }
        #pragma unroll
        for (int o = 16; o > 0; o >>= 1)
            #pragma unroll
            for (int l = 0; l < 16; l++)
                acc[l] += __shfl_xor_sync(0xffffffffu, acc[l], o);

        if (lane < 16) {
            float v[16], m = -1e30f;
            #pragma unroll
            for (int l = 0; l < 16; l++) { v[l] = acc[l] + gb[l]; m = fmaxf(m, v[l]); }
            float s = 0.f;
            #pragma unroll
            for (int l = 0; l < 16; l++) { v[l] = __expf(v[l] - m); s += v[l]; }
            g_gate[row * NL + lane] = v[lane] / s;
        }
    }
}

// ---------------------------------------------------------------------------
// main GEMM: out = Y @ PW^T + g @ pb^T via mma.sync fp16 m16n8k16, fp32 accum
//   BK=64 per iter (4 k16-steps), 3 smem bufs, distance-1 cp.async pipeline.
// ---------------------------------------------------------------------------
__global__ __launch_bounds__(256, 1)
void moe_mma_kernel(float* __restrict__ out) {
    extern __shared__ char smc[];
    float* gs = (float*)(smc + GS_OFF);

    const int tid  = threadIdx.x;
    const int warp = tid >> 5, lane = tid & 31;
    const int m_blk = blockIdx.y * BM;
    const int n_blk = blockIdx.x * BN;
    const int warpM = warp & 1, warpN = warp >> 1;

    // ---- g tile -> smem (pitch 20 floats) ----
    for (int idx = tid; idx < BM * NL; idx += 256) {
        int m = idx >> 4, l = idx & 15;
        gs[m * GS_PITCH + l] = g_gate[(size_t)(m_blk + m) * NL + l];
    }

    // roles
    const int q = lane >> 2, cc = lane & 3;
    const int gm0 = warp * 16 + q, gm1 = gm0 + 8;   // generator rows (mtile=warp)
    const int f8 = tid & 7, rb = tid >> 3;          // B loader
    const int bq = lane >> 2, bc = lane & 3;        // B fragment reader

    auto loadB = [&](int c, int buf) {
        const __half* src = g_pwh + (size_t)n_blk * KCAT + (size_t)c * BK;
        uint32_t dst = smem_u32_of(smc + B_OFF + buf * B_BUF_B);
        #pragma unroll
        for (int qq = 0; qq < 8; qq++) {
            int row = rb + qq * 32;
            cp_async16(dst + (uint32_t)(row * 144 + f8 * 16),
                       src + (size_t)row * KCAT + f8 * 8);
        }
        asm volatile("cp.async.commit_group;" ::: "memory");
    };
    auto loadB_bias = [&](int buf) {
        int f2 = tid & 1, rbb = tid >> 1;
        uint32_t dst = smem_u32_of(smc + B_OFF + buf * B_BUF_B);
        #pragma unroll
        for (int qq = 0; qq < 2; qq++) {
            int row = rbb + qq * 128;
            cp_async16(dst + (uint32_t)(row * 144 + f2 * 16),
                       g_pbh + (size_t)(n_blk + row) * NL + f2 * 8);
        }
        asm volatile("cp.async.commit_group;" ::: "memory");
    };
    auto fetchX = [&](int c, float4& xa, float4& xb) {
        const float* p = g_xT + (size_t)(4 * c) * BATCH + m_blk;
        xa = make_float4(__ldg(p + gm0), __ldg(p + BATCH + gm0),
                         __ldg(p + 2 * BATCH + gm0), __ldg(p + 3 * BATCH + gm0));
        xb = make_float4(__ldg(p + gm1), __ldg(p + BATCH + gm1),
                         __ldg(p + 2 * BATCH + gm1), __ldg(p + 3 * BATCH + gm1));
    };
    auto genA = [&](int buf, float4 xa, float4 xb) {
        // g values for this thread's fragment columns
        float2 t0 = *(float2*)(gs + gm0 * GS_PITCH + 2 * cc);       // l=2cc,2cc+1
        float2 t1 = *(float2*)(gs + gm0 * GS_PITCH + 2 * cc + 8);   // l=2cc+8,+9
        float2 t2 = *(float2*)(gs + gm1 * GS_PITCH + 2 * cc);
        float2 t3 = *(float2*)(gs + gm1 * GS_PITCH + 2 * cc + 8);
        float xav[4] = {xa.x, xa.y, xa.z, xa.w};
        float xbv[4] = {xb.x, xb.y, xb.z, xb.w};
        uint4* base = (uint4*)(smc + A_OFF + buf * A_BUF_B);
        #pragma unroll
        for (int ks = 0; ks < 4; ks++) {
            float x0 = xav[ks], x1 = xbv[ks];
            uint4 v;
            v.x = h2u(x0 * t0.x, x0 * t0.y);   // a0: row gm0, k=2cc,2cc+1
            v.y = h2u(x1 * t2.x, x1 * t2.y);   // a1: row gm1
            v.z = h2u(x0 * t1.x, x0 * t1.y);   // a2: row gm0, k=+8
            v.w = h2u(x1 * t3.x, x1 * t3.y);   // a3: row gm1, k=+8
            base[(warp * 4 + ks) * 32 + lane] = v;
        }
    };
    auto genA_bias = [&](int buf) {
        float2 t0 = *(float2*)(gs + gm0 * GS_PITCH + 2 * cc);
        float2 t1 = *(float2*)(gs + gm0 * GS_PITCH + 2 * cc + 8);
        float2 t2 = *(float2*)(gs + gm1 * GS_PITCH + 2 * cc);
        float2 t3 = *(float2*)(gs + gm1 * GS_PITCH + 2 * cc + 8);
        uint4 v;
        v.x = h2u(t0.x, t0.y); v.y = h2u(t2.x, t2.y);
        v.z = h2u(t1.x, t1.y); v.w = h2u(t3.x, t3.y);
        ((uint4*)(smc + A_OFF + buf * A_BUF_B))[(warp * 4 + 0) * 32 + lane] = v;
    };

    float acc[4][8][4];
    #pragma unroll
    for (int mt = 0; mt < 4; mt++)
        #pragma unroll
        for (int nt = 0; nt < 8; nt++)
            #pragma unroll
            for (int j = 0; j < 4; j++) acc[mt][nt][j] = 0.f;

    auto compute = [&](int buf, int nks) {
        const uint4* Ab = (const uint4*)(smc + A_OFF + buf * A_BUF_B);
        const uint32_t* Bw = (const uint32_t*)(smc + B_OFF + buf * B_BUF_B);
        for (int ks = 0; ks < nks; ks++) {
            uint4 a[4];
            #pragma unroll
            for (int mt = 0; mt < 4; mt++)
                a[mt] = Ab[((warpM * 4 + mt) * 4 + ks) * 32 + lane];
            uint32_t b[8][2];
            #pragma unroll
            for (int nt = 0; nt < 8; nt++) {
                int row = warpN * 64 + nt * 8 + bq;
                b[nt][0] = Bw[row * 36 + ks * 8 + bc];
                b[nt][1] = Bw[row * 36 + ks * 8 + 4 + bc];
            }
            #pragma unroll
            for (int mt = 0; mt < 4; mt++)
                #pragma unroll
                for (int nt = 0; nt < 8; nt++)
                    mma_f16(acc[mt][nt], a[mt], b[nt][0], b[nt][1]);
        }
    };

    // ---- prologue ----
    loadB(0, 0);
    float4 xa, xb, xa2, xb2;
    fetchX(0, xa, xb);
    __syncthreads();              // gs visible
    genA(0, xa, xb);
    fetchX(1, xa, xb);

    // ---- main loop: distance-1, one barrier per iteration ----
    #pragma unroll 1
    for (int it = 0; it < NTOT; it++) {
        const int nc = it + 1;
        if (nc < NIT) {
            loadB(nc, nc % 3);
            if (nc + 1 < NIT) fetchX(nc + 1, xa2, xb2);
            genA(nc % 3, xa, xb);
            xa = xa2; xb = xb2;
        } else if (nc == NIT) {
            loadB_bias(nc % 3);
            genA_bias(nc % 3);
        }
        if (nc <= NIT) asm volatile("cp.async.wait_group 1;" ::: "memory");
        else           asm volatile("cp.async.wait_group 0;" ::: "memory");
        __syncthreads();
        compute(it % 3, (it == NIT) ? 1 : 4);
    }

    // ---- epilogue: fragment store, 8B quad-coalesced ----
    #pragma unroll
    for (int mt = 0; mt < 4; mt++) {
        int m0 = m_blk + warpM * 64 + mt * 16 + (lane >> 2);
        #pragma unroll
        for (int nt = 0; nt < 8; nt++) {
            int n = n_blk + warpN * 64 + nt * 8 + 2 * (lane & 3);
            *(float2*)(out + (size_t)m0 * OUTF + n)       = make_float2(acc[mt][nt][0], acc[mt][nt][1]);
            *(float2*)(out + (size_t)(m0 + 8) * OUTF + n) = make_float2(acc[mt][nt][2], acc[mt][nt][3]);
        }
    }
}

// ---------------------------------------------------------------------------
extern "C" void kernel_launch(void* const* d_in, const int* in_sizes, int n_in,
                              void* d_out, int out_size) {
    const float* x  = (const float*)d_in[0];
    const float* gw = (const float*)d_in[1];
    const float* gb = (const float*)d_in[2];
    const float* pw = (const float*)d_in[3];
    const float* pb = (const float*)d_in[4];
    float* out = (float*)d_out;

    cudaFuncSetAttribute(gating_kernel, cudaFuncAttributeMaxDynamicSharedMemorySize,
                         INF * 17 * 4);
    cudaFuncSetAttribute(moe_mma_kernel, cudaFuncAttributeMaxDynamicSharedMemorySize,
                         SMEM_TOTAL);

    gating_kernel<<<BATCH / 32, 256, INF * 17 * 4>>>(x, gw, gb);
    transpose_x_kernel<<<dim3(INF / 32, BATCH / 32), dim3(32, 8)>>>(x);
    conv_pw_kernel<<<((size_t)OUTF * KCAT) / 8 / 256, 256>>>(pw);
    conv_pb_kernel<<<(OUTF * NL) / 8 / 256, 256>>>(pb);

    dim3 grid(OUTF / BN, BATCH / BM);   // (4, 32) = 128 CTAs, single wave
    moe_mma_kernel<<<grid, 256, SMEM_TOTAL>>>(out);
}

// round 7
// speedup vs baseline: 2.5855x; 1.2709x over previous
#include <cuda_runtime.h>
#include <cuda_fp16.h>
#include <cstdint>

#define BATCH 4096
#define INF   1024
#define OUTF  1024
#define NL    16

#define BM 128
#define BN 128
#define BK 64                  // kcat per chunk = 4 i-values x 16 leaves
#define NIT (INF/4)            // 256 pw chunks
#define NTOT (NIT+1)           // +1 bias tile
#define KCAT (INF*NL)

// smem layout (bytes)
#define A_BUF_B   16384        // 8 mtiles x 4 ksteps x 32 lanes x 16B
#define B_BUF_B   (BN*144)     // 18432 (row pitch 144B, conflict-free)
#define A_OFF     0
#define B_OFF     (3*A_BUF_B)              // 49152
#define GS_OFF    (B_OFF + 3*B_BUF_B)      // 104448
#define GS_PITCH  20
#define SMEM_TOTAL (GS_OFF + BM*GS_PITCH*4)  // 114688 bytes (112KB) -> 2 CTA/SM

#define NPW_BLOCKS (((size_t)OUTF*KCAT)/8/256)   // 8192

// device scratch (allocation-free)
__device__ float  g_gate[BATCH * NL];
__device__ float  g_xT[INF * BATCH];          // x transposed [i][b]
__device__ __half g_pwh[(size_t)OUTF * KCAT]; // pw in fp16
__device__ __half g_pbh[OUTF * NL];           // pb in fp16

__device__ __forceinline__ uint32_t smem_u32_of(const void* p) {
    uint32_t a;
    asm("{ .reg .u64 t; cvta.to.shared.u64 t, %1; cvt.u32.u64 %0, t; }" : "=r"(a) : "l"(p));
    return a;
}
__device__ __forceinline__ uint32_t h2u(float lo, float hi) {
    __half2 h = __floats2half2_rn(lo, hi);
    return *(uint32_t*)&h;
}
__device__ __forceinline__ void cp_async16(uint32_t sa, const void* ga) {
    asm volatile("cp.async.cg.shared.global [%0], [%1], 16;" :: "r"(sa), "l"(ga));
}
__device__ __forceinline__ void mma_f16(float* c, const uint4& a, uint32_t b0, uint32_t b1) {
    asm volatile(
        "mma.sync.aligned.m16n8k16.row.col.f32.f16.f16.f32 "
        "{%0,%1,%2,%3}, {%4,%5,%6,%7}, {%8,%9}, {%0,%1,%2,%3};"
        : "+f"(c[0]), "+f"(c[1]), "+f"(c[2]), "+f"(c[3])
        : "r"(a.x), "r"(a.y), "r"(a.z), "r"(a.w), "r"(b0), "r"(b1));
}
__device__ __forceinline__ void ldsm_x4(uint32_t& r0, uint32_t& r1, uint32_t& r2, uint32_t& r3,
                                        uint32_t addr) {
    asm volatile("ldmatrix.sync.aligned.m8n8.x4.shared.b16 {%0,%1,%2,%3}, [%4];"
                 : "=r"(r0), "=r"(r1), "=r"(r2), "=r"(r3) : "r"(addr));
}

// ---------------------------------------------------------------------------
// x transpose: g_xT[i][b] = x[b][i]
// ---------------------------------------------------------------------------
__global__ __launch_bounds__(256)
void transpose_x_kernel(const float* __restrict__ x) {
    __shared__ float t[32][33];
    int i0 = blockIdx.x * 32, b0 = blockIdx.y * 32;
    int tx = threadIdx.x, ty = threadIdx.y;      // 32 x 8
    #pragma unroll
    for (int j = 0; j < 32; j += 8)
        t[ty + j][tx] = x[(size_t)(b0 + ty + j) * INF + i0 + tx];
    __syncthreads();
    #pragma unroll
    for (int j = 0; j < 32; j += 8)
        g_xT[(size_t)(i0 + ty + j) * BATCH + b0 + tx] = t[tx][ty + j];
}

// ---------------------------------------------------------------------------
// pw, pb -> fp16 (single launch)
// ---------------------------------------------------------------------------
__global__ __launch_bounds__(256)
void conv_kernel(const float* __restrict__ pw, const float* __restrict__ pb) {
    size_t bid = blockIdx.x;
    if (bid < NPW_BLOCKS) {
        size_t idx = bid * 256 + threadIdx.x;    // 8 floats per thread
        float4 v0 = ((const float4*)pw)[idx * 2];
        float4 v1 = ((const float4*)pw)[idx * 2 + 1];
        uint4 o;
        o.x = h2u(v0.x, v0.y); o.y = h2u(v0.z, v0.w);
        o.z = h2u(v1.x, v1.y); o.w = h2u(v1.z, v1.w);
        ((uint4*)g_pwh)[idx] = o;
    } else {
        size_t idx = (bid - NPW_BLOCKS) * 256 + threadIdx.x;
        float4 v0 = ((const float4*)pb)[idx * 2];
        float4 v1 = ((const float4*)pb)[idx * 2 + 1];
        uint4 o;
        o.x = h2u(v0.x, v0.y); o.y = h2u(v0.z, v0.w);
        o.z = h2u(v1.x, v1.y); o.w = h2u(v1.z, v1.w);
        ((uint4*)g_pbh)[idx] = o;
    }
}

// ---------------------------------------------------------------------------
// gating: g = softmax(x @ gw + gb). 4 rows per warp (amortize gw smem load).
// ---------------------------------------------------------------------------
__global__ __launch_bounds__(256)
void gating_kernel(const float* __restrict__ x,
                   const float* __restrict__ gw,
                   const float* __restrict__ gb) {
    extern __shared__ float gw_s[];   // [1024][17]
    int tid = threadIdx.x, warp = tid >> 5, lane = tid & 31;

    for (int idx = tid; idx < INF * NL; idx += 256) {
        int i = idx >> 4, l = idx & 15;
        gw_s[i * 17 + l] = gw[idx];
    }
    __syncthreads();

    #pragma unroll 1
    for (int r = 0; r < 4; r++) {
        int row = blockIdx.x * 32 + warp * 4 + r;
        const float* xr = x + (size_t)row * INF;

        float acc[16];
        #pragma unroll
        for (int l = 0; l < 16; l++) acc[l] = 0.f;

        #pragma unroll 4
        for (int jj = 0; jj < 32; jj++) {
            int i = lane + 32 * jj;
            float xv = xr[i];
            const float* gr = gw_s + i * 17;
            #pragma unroll
            for (int l = 0; l < 16; l++) acc[l] = fmaf(xv, gr[l], acc[l]);
        }
        #pragma unroll
        for (int o = 16; o > 0; o >>= 1)
            #pragma unroll
            for (int l = 0; l < 16; l++)
                acc[l] += __shfl_xor_sync(0xffffffffu, acc[l], o);

        if (lane < 16) {
            float v[16], m = -1e30f;
            #pragma unroll
            for (int l = 0; l < 16; l++) { v[l] = acc[l] + gb[l]; m = fmaxf(m, v[l]); }
            float s = 0.f;
            #pragma unroll
            for (int l = 0; l < 16; l++) { v[l] = __expf(v[l] - m); s += v[l]; }
            g_gate[row * NL + lane] = v[lane] / s;
        }
    }
}

// ---------------------------------------------------------------------------
// main GEMM: out = Y @ PW^T + g @ pb^T via mma.sync fp16 m16n8k16, fp32 accum
// 128x128 tile, 2 CTAs/SM, ldmatrix.x4 B fragments, distance-1 pipeline.
// ---------------------------------------------------------------------------
__global__ __launch_bounds__(256, 2)
void moe_mma_kernel(float* __restrict__ out) {
    extern __shared__ char smc[];
    float* gs = (float*)(smc + GS_OFF);

    const int tid  = threadIdx.x;
    const int warp = tid >> 5, lane = tid & 31;
    const int m_blk = blockIdx.y * BM;
    const int n_blk = blockIdx.x * BN;
    const int warpM = warp & 1, warpN = warp >> 1;   // 2 x 4 warp grid, 64x32 each

    // ---- g tile -> smem (pitch 20 floats) ----
    for (int idx = tid; idx < BM * NL; idx += 256) {
        int m = idx >> 4, l = idx & 15;
        gs[m * GS_PITCH + l] = g_gate[(size_t)(m_blk + m) * NL + l];
    }

    // roles
    const int q = lane >> 2, cc = lane & 3;
    const int gm0 = warp * 16 + q, gm1 = gm0 + 8;   // generator rows (mtile=warp)
    const int f8 = tid & 7, rb = tid >> 3;          // B loader

    auto loadB = [&](int c, int buf) {
        const __half* src = g_pwh + (size_t)n_blk * KCAT + (size_t)c * BK;
        uint32_t dst = smem_u32_of(smc + B_OFF + buf * B_BUF_B);
        #pragma unroll
        for (int qq = 0; qq < 4; qq++) {
            int row = rb + qq * 32;
            cp_async16(dst + (uint32_t)(row * 144 + f8 * 16),
                       src + (size_t)row * KCAT + f8 * 8);
        }
        asm volatile("cp.async.commit_group;" ::: "memory");
    };
    auto loadB_bias = [&](int buf) {
        int f2 = tid & 1, row = tid >> 1;     // 128 rows x 32B
        uint32_t dst = smem_u32_of(smc + B_OFF + buf * B_BUF_B);
        cp_async16(dst + (uint32_t)(row * 144 + f2 * 16),
                   g_pbh + (size_t)(n_blk + row) * NL + f2 * 8);
        asm volatile("cp.async.commit_group;" ::: "memory");
    };
    auto fetchX = [&](int c, float4& xa, float4& xb) {
        const float* p = g_xT + (size_t)(4 * c) * BATCH + m_blk;
        xa = make_float4(__ldg(p + gm0), __ldg(p + BATCH + gm0),
                         __ldg(p + 2 * BATCH + gm0), __ldg(p + 3 * BATCH + gm0));
        xb = make_float4(__ldg(p + gm1), __ldg(p + BATCH + gm1),
                         __ldg(p + 2 * BATCH + gm1), __ldg(p + 3 * BATCH + gm1));
    };
    auto genA = [&](int buf, float4 xa, float4 xb) {
        float2 t0 = *(float2*)(gs + gm0 * GS_PITCH + 2 * cc);       // l=2cc,2cc+1
        float2 t1 = *(float2*)(gs + gm0 * GS_PITCH + 2 * cc + 8);   // l=+8
        float2 t2 = *(float2*)(gs + gm1 * GS_PITCH + 2 * cc);
        float2 t3 = *(float2*)(gs + gm1 * GS_PITCH + 2 * cc + 8);
        float xav[4] = {xa.x, xa.y, xa.z, xa.w};
        float xbv[4] = {xb.x, xb.y, xb.z, xb.w};
        uint4* base = (uint4*)(smc + A_OFF + buf * A_BUF_B);
        #pragma unroll
        for (int ks = 0; ks < 4; ks++) {
            float x0 = xav[ks], x1 = xbv[ks];
            uint4 v;
            v.x = h2u(x0 * t0.x, x0 * t0.y);
            v.y = h2u(x1 * t2.x, x1 * t2.y);
            v.z = h2u(x0 * t1.x, x0 * t1.y);
            v.w = h2u(x1 * t3.x, x1 * t3.y);
            base[(warp * 4 + ks) * 32 + lane] = v;
        }
    };
    auto genA_bias = [&](int buf) {
        float2 t0 = *(float2*)(gs + gm0 * GS_PITCH + 2 * cc);
        float2 t1 = *(float2*)(gs + gm0 * GS_PITCH + 2 * cc + 8);
        float2 t2 = *(float2*)(gs + gm1 * GS_PITCH + 2 * cc);
        float2 t3 = *(float2*)(gs + gm1 * GS_PITCH + 2 * cc + 8);
        uint4 v;
        v.x = h2u(t0.x, t0.y); v.y = h2u(t2.x, t2.y);
        v.z = h2u(t1.x, t1.y); v.w = h2u(t3.x, t3.y);
        ((uint4*)(smc + A_OFF + buf * A_BUF_B))[(warp * 4 + 0) * 32 + lane] = v;
    };

    float acc[4][4][4];
    #pragma unroll
    for (int mt = 0; mt < 4; mt++)
        #pragma unroll
        for (int nt = 0; nt < 4; nt++)
            #pragma unroll
            for (int j = 0; j < 4; j++) acc[mt][nt][j] = 0.f;

    // B ldmatrix per-thread base: row/col assignment for x4
    const int lrow = warpN * 32 + (lane & 7) + ((lane >> 4) << 3);
    const uint32_t lcol16 = ((lane >> 3) & 1) << 4;       // byte offset for k-half
    const uint32_t bB0 = smem_u32_of(smc + B_OFF) + (uint32_t)lrow * 144 + lcol16;

    auto compute = [&](int bufB, int bufA, int nks) {
        const uint4* Ab = (const uint4*)(smc + A_OFF + bufA * A_BUF_B);
        const uint32_t bb = bB0 + (uint32_t)bufB * B_BUF_B;
        for (int ks = 0; ks < nks; ks++) {
            uint4 a[4];
            #pragma unroll
            for (int mt = 0; mt < 4; mt++)
                a[mt] = Ab[((warpM * 4 + mt) * 4 + ks) * 32 + lane];
            uint32_t b[4][2];
            ldsm_x4(b[0][0], b[0][1], b[1][0], b[1][1], bb + ks * 32);
            ldsm_x4(b[2][0], b[2][1], b[3][0], b[3][1], bb + 16 * 144 + ks * 32);
            #pragma unroll
            for (int mt = 0; mt < 4; mt++)
                #pragma unroll
                for (int nt = 0; nt < 4; nt++)
                    mma_f16(acc[mt][nt], a[mt], b[nt][0], b[nt][1]);
        }
    };

    // ---- prologue ----
    loadB(0, 0);
    float4 xa, xb, xa2, xb2;
    fetchX(0, xa, xb);
    __syncthreads();              // gs visible
    genA(0, xa, xb);
    fetchX(1, xa, xb);

    // ---- main loop: distance-1, one barrier per iteration ----
    #pragma unroll 1
    for (int it = 0; it < NTOT; it++) {
        const int nc = it + 1;
        if (nc < NIT) {
            loadB(nc, nc % 3);
            if (nc + 1 < NIT) fetchX(nc + 1, xa2, xb2);
            genA(nc % 3, xa, xb);
            xa = xa2; xb = xb2;
        } else if (nc == NIT) {
            loadB_bias(nc % 3);
            genA_bias(nc % 3);
        }
        if (nc <= NIT) asm volatile("cp.async.wait_group 1;" ::: "memory");
        else           asm volatile("cp.async.wait_group 0;" ::: "memory");
        __syncthreads();
        compute(it % 3, it % 3, (it == NIT) ? 1 : 4);
    }

    // ---- epilogue: fragment store, 8B quad-coalesced ----
    #pragma unroll
    for (int mt = 0; mt < 4; mt++) {
        int m0 = m_blk + warpM * 64 + mt * 16 + (lane >> 2);
        #pragma unroll
        for (int nt = 0; nt < 4; nt++) {
            int n = n_blk + warpN * 32 + nt * 8 + 2 * (lane & 3);
            *(float2*)(out + (size_t)m0 * OUTF + n)       = make_float2(acc[mt][nt][0], acc[mt][nt][1]);
            *(float2*)(out + (size_t)(m0 + 8) * OUTF + n) = make_float2(acc[mt][nt][2], acc[mt][nt][3]);
        }
    }
}

// ---------------------------------------------------------------------------
extern "C" void kernel_launch(void* const* d_in, const int* in_sizes, int n_in,
                              void* d_out, int out_size) {
    const float* x  = (const float*)d_in[0];
    const float* gw = (const float*)d_in[1];
    const float* gb = (const float*)d_in[2];
    const float* pw = (const float*)d_in[3];
    const float* pb = (const float*)d_in[4];
    float* out = (float*)d_out;

    cudaFuncSetAttribute(gating_kernel, cudaFuncAttributeMaxDynamicSharedMemorySize,
                         INF * 17 * 4);
    cudaFuncSetAttribute(moe_mma_kernel, cudaFuncAttributeMaxDynamicSharedMemorySize,
                         SMEM_TOTAL);

    gating_kernel<<<BATCH / 32, 256, INF * 17 * 4>>>(x, gw, gb);
    transpose_x_kernel<<<dim3(INF / 32, BATCH / 32), dim3(32, 8)>>>(x);
    conv_kernel<<<NPW_BLOCKS + (OUTF * NL) / 8 / 256, 256>>>(pw, pb);

    dim3 grid(OUTF / BN, BATCH / BM);   // (8, 32) = 256 CTAs, 2/SM, one wave
    moe_mma_kernel<<<grid, 256, SMEM_TOTAL>>>(out);
}

// round 9
// speedup vs baseline: 2.9167x; 1.1281x over previous
#include <cuda_runtime.h>
#include <cuda_fp16.h>
#include <cstdint>

#define BATCH 4096
#define INF   1024
#define OUTF  1024
#define NL    16

#define BM 128
#define BN 128
#define BK 64                  // 4 i-values x 16 leaves per chunk
#define NIT (INF/4)            // 256 pw chunks
#define KCAT (INF*NL)

// smem layout (bytes)
#define X_OFF    0
#define X_BUF_B  1024          // 128 rows x 4 i x fp16
#define B_OFF    (3*X_BUF_B)   // 3072 (128B-aligned)
#define B_BUF_B  (BN*144)      // 18432 (144B pitch, LDSM conflict-free)
#define SMEM_TOTAL (B_OFF + 3*B_BUF_B)   // 58368 bytes

#define NPW_BLOCKS ((size_t)OUTF*KCAT/8/256)   // 8192
#define NX_BLOCKS  ((size_t)BATCH*INF/8/256)   // 2048

// device scratch (allocation-free)
__device__ __half g_gh[BATCH * NL];            // gating in fp16
__device__ __half g_xh[(size_t)BATCH * INF];   // x in fp16 (row-major)
__device__ __half g_pwh[(size_t)OUTF * KCAT];  // pw in fp16
__device__ __half g_pbh[OUTF * NL];            // pb in fp16

__device__ __forceinline__ uint32_t smem_u32_of(const void* p) {
    uint32_t a;
    asm("{ .reg .u64 t; cvta.to.shared.u64 t, %1; cvt.u32.u64 %0, t; }" : "=r"(a) : "l"(p));
    return a;
}
__device__ __forceinline__ uint32_t h2u(float lo, float hi) {
    __half2 h = __floats2half2_rn(lo, hi);
    return *(uint32_t*)&h;
}
__device__ __forceinline__ uint32_t hu(__half2 h) { return *(uint32_t*)&h; }
__device__ __forceinline__ void cp_async16(uint32_t sa, const void* ga) {
    asm volatile("cp.async.cg.shared.global [%0], [%1], 16;" :: "r"(sa), "l"(ga));
}
__device__ __forceinline__ void cp_async8(uint32_t sa, const void* ga) {
    asm volatile("cp.async.ca.shared.global [%0], [%1], 8;" :: "r"(sa), "l"(ga));
}
__device__ __forceinline__ void mma_f16(float* c, uint32_t a0, uint32_t a1,
                                        uint32_t a2, uint32_t a3,
                                        uint32_t b0, uint32_t b1) {
    asm volatile(
        "mma.sync.aligned.m16n8k16.row.col.f32.f16.f16.f32 "
        "{%0,%1,%2,%3}, {%4,%5,%6,%7}, {%8,%9}, {%0,%1,%2,%3};"
        : "+f"(c[0]), "+f"(c[1]), "+f"(c[2]), "+f"(c[3])
        : "r"(a0), "r"(a1), "r"(a2), "r"(a3), "r"(b0), "r"(b1));
}
__device__ __forceinline__ void ldsm_x4(uint32_t& r0, uint32_t& r1, uint32_t& r2, uint32_t& r3,
                                        uint32_t addr) {
    asm volatile("ldmatrix.sync.aligned.m8n8.x4.shared.b16 {%0,%1,%2,%3}, [%4];"
                 : "=r"(r0), "=r"(r1), "=r"(r2), "=r"(r3) : "r"(addr));
}

// ---------------------------------------------------------------------------
// prep: pw, x, pb -> fp16 (single launch, three grid sections)
// ---------------------------------------------------------------------------
__global__ __launch_bounds__(256)
void conv_kernel(const float* __restrict__ pw, const float* __restrict__ x,
                 const float* __restrict__ pb) {
    size_t bid = blockIdx.x;
    const float* src;
    __half* dst;
    size_t idx;
    if (bid < NPW_BLOCKS)            { src = pw; dst = g_pwh; idx = bid * 256 + threadIdx.x; }
    else if (bid < NPW_BLOCKS + NX_BLOCKS)
                                     { src = x;  dst = g_xh;  idx = (bid - NPW_BLOCKS) * 256 + threadIdx.x; }
    else                             { src = pb; dst = g_pbh; idx = (bid - NPW_BLOCKS - NX_BLOCKS) * 256 + threadIdx.x; }
    float4 v0 = ((const float4*)src)[idx * 2];
    float4 v1 = ((const float4*)src)[idx * 2 + 1];
    uint4 o;
    o.x = h2u(v0.x, v0.y); o.y = h2u(v0.z, v0.w);
    o.z = h2u(v1.x, v1.y); o.w = h2u(v1.z, v1.w);
    ((uint4*)dst)[idx] = o;
}

// ---------------------------------------------------------------------------
// gating: g = softmax(x @ gw + gb) -> fp16. 4 rows per warp.
// ---------------------------------------------------------------------------
__global__ __launch_bounds__(256)
void gating_kernel(const float* __restrict__ x,
                   const float* __restrict__ gw,
                   const float* __restrict__ gb) {
    extern __shared__ float gw_s[];   // [1024][17]
    int tid = threadIdx.x, warp = tid >> 5, lane = tid & 31;

    for (int idx = tid; idx < INF * NL; idx += 256) {
        int i = idx >> 4, l = idx & 15;
        gw_s[i * 17 + l] = gw[idx];
    }
    __syncthreads();

    #pragma unroll 1
    for (int r = 0; r < 4; r++) {
        int row = blockIdx.x * 32 + warp * 4 + r;
        const float* xr = x + (size_t)row * INF;

        float acc[16];
        #pragma unroll
        for (int l = 0; l < 16; l++) acc[l] = 0.f;

        #pragma unroll 4
        for (int jj = 0; jj < 32; jj++) {
            int i = lane + 32 * jj;
            float xv = xr[i];
            const float* gr = gw_s + i * 17;
            #pragma unroll
            for (int l = 0; l < 16; l++) acc[l] = fmaf(xv, gr[l], acc[l]);
        }
        #pragma unroll
        for (int o = 16; o > 0; o >>= 1)
            #pragma unroll
            for (int l = 0; l < 16; l++)
                acc[l] += __shfl_xor_sync(0xffffffffu, acc[l], o);

        if (lane < 16) {
            float v[16], m = -1e30f;
            #pragma unroll
            for (int l = 0; l < 16; l++) { v[l] = acc[l] + gb[l]; m = fmaxf(m, v[l]); }
            float s = 0.f;
            #pragma unroll
            for (int l = 0; l < 16; l++) { v[l] = __expf(v[l] - m); s += v[l]; }
            g_gh[row * NL + lane] = __float2half(v[lane] / s);
        }
    }
}

// ---------------------------------------------------------------------------
// main GEMM: out = Y @ PW^T + g @ pb^T, mma.sync fp16 m16n8k16, fp32 accum.
// A fragments generated IN REGISTERS per warp (g in regs, x via 1KB smem tile)
// — no A smem round trip. B via cp.async + ldmatrix.x4, 3-buf distance-1.
// ---------------------------------------------------------------------------
__global__ __launch_bounds__(256, 2)
void moe_mma_kernel(float* __restrict__ out) {
    extern __shared__ char smc[];

    const int tid  = threadIdx.x;
    const int warp = tid >> 5, lane = tid & 31;
    const int m_blk = blockIdx.y * BM;
    const int n_blk = blockIdx.x * BN;
    const int warpM = warp & 1, warpN = warp >> 1;   // 2 x 4 warp grid, 64x32 each

    const int q = lane >> 2, cc = lane & 3;
    const int f8 = tid & 7, rb = tid >> 3;          // B loader roles

    // ---- g fragment pairs in registers (k-invariant) ----
    __half2 tg[4][4];
    #pragma unroll
    for (int mt = 0; mt < 4; mt++) {
        int r0 = m_blk + warpM * 64 + mt * 16 + q;
        int r1 = r0 + 8;
        tg[mt][0] = *(const __half2*)(g_gh + r0 * NL + 2 * cc);
        tg[mt][1] = *(const __half2*)(g_gh + r1 * NL + 2 * cc);
        tg[mt][2] = *(const __half2*)(g_gh + r0 * NL + 2 * cc + 8);
        tg[mt][3] = *(const __half2*)(g_gh + r1 * NL + 2 * cc + 8);
    }

    auto loadX = [&](int c, int buf) {
        if (tid < 128)
            cp_async8(smem_u32_of(smc + X_OFF + buf * X_BUF_B) + (uint32_t)tid * 8,
                      g_xh + (size_t)(m_blk + tid) * INF + c * 4);
    };
    auto loadB = [&](int c, int buf) {
        const __half* src = g_pwh + (size_t)n_blk * KCAT + (size_t)c * BK;
        uint32_t dst = smem_u32_of(smc + B_OFF + buf * B_BUF_B);
        #pragma unroll
        for (int qq = 0; qq < 4; qq++) {
            int row = rb + qq * 32;
            cp_async16(dst + (uint32_t)(row * 144 + f8 * 16),
                       src + (size_t)row * KCAT + f8 * 8);
        }
    };
    auto loadB_bias = [&](int buf) {
        int f2 = tid & 1, row = tid >> 1;     // 128 rows x 32B
        uint32_t dst = smem_u32_of(smc + B_OFF + buf * B_BUF_B);
        cp_async16(dst + (uint32_t)(row * 144 + f2 * 16),
                   g_pbh + (size_t)(n_blk + row) * NL + f2 * 8);
    };

    float acc[4][4][4];
    #pragma unroll
    for (int mt = 0; mt < 4; mt++)
        #pragma unroll
        for (int nt = 0; nt < 4; nt++)
            #pragma unroll
            for (int j = 0; j < 4; j++) acc[mt][nt][j] = 0.f;

    // B ldmatrix per-thread base (proven mapping from R6)
    const int lrow = warpN * 32 + (lane & 7) + ((lane >> 4) << 3);
    const uint32_t lcol16 = ((lane >> 3) & 1) << 4;
    const uint32_t bB0 = smem_u32_of(smc + B_OFF) + (uint32_t)lrow * 144 + lcol16;

    auto compute = [&](int buf) {
        const char* xt = smc + X_OFF + buf * X_BUF_B + (warpM * 64) * 8;
        // x row-pairs: xp = row gm0 (i0,i1)(i2,i3); xq = row gm1
        __half2 xp0[4], xp1[4], xq0[4], xq1[4];
        #pragma unroll
        for (int mt = 0; mt < 4; mt++) {
            const __half2* p  = (const __half2*)(xt + (mt * 16 + q) * 8);
            const __half2* pq = (const __half2*)(xt + (mt * 16 + q + 8) * 8);
            xp0[mt] = p[0];  xp1[mt] = p[1];
            xq0[mt] = pq[0]; xq1[mt] = pq[1];
        }
        const uint32_t bb = bB0 + (uint32_t)buf * B_BUF_B;
        #pragma unroll
        for (int ks = 0; ks < 4; ks++) {
            uint32_t b[4][2];
            ldsm_x4(b[0][0], b[0][1], b[1][0], b[1][1], bb + ks * 32);
            ldsm_x4(b[2][0], b[2][1], b[3][0], b[3][1], bb + 16 * 144 + ks * 32);
            #pragma unroll
            for (int mt = 0; mt < 4; mt++) {
                __half2 xs0 = (ks == 0) ? __low2half2(xp0[mt]) :
                              (ks == 1) ? __high2half2(xp0[mt]) :
                              (ks == 2) ? __low2half2(xp1[mt]) : __high2half2(xp1[mt]);
                __half2 xs1 = (ks == 0) ? __low2half2(xq0[mt]) :
                              (ks == 1) ? __high2half2(xq0[mt]) :
                              (ks == 2) ? __low2half2(xq1[mt]) : __high2half2(xq1[mt]);
                uint32_t a0 = hu(__hmul2(xs0, tg[mt][0]));
                uint32_t a1 = hu(__hmul2(xs1, tg[mt][1]));
                uint32_t a2 = hu(__hmul2(xs0, tg[mt][2]));
                uint32_t a3 = hu(__hmul2(xs1, tg[mt][3]));
                #pragma unroll
                for (int nt = 0; nt < 4; nt++)
                    mma_f16(acc[mt][nt], a0, a1, a2, a3, b[nt][0], b[nt][1]);
            }
        }
    };
    auto compute_bias = [&](int buf) {
        const uint32_t bb = bB0 + (uint32_t)buf * B_BUF_B;
        uint32_t b[4][2];
        ldsm_x4(b[0][0], b[0][1], b[1][0], b[1][1], bb);
        ldsm_x4(b[2][0], b[2][1], b[3][0], b[3][1], bb + 16 * 144);
        #pragma unroll
        for (int mt = 0; mt < 4; mt++) {
            uint32_t a0 = hu(tg[mt][0]), a1 = hu(tg[mt][1]);
            uint32_t a2 = hu(tg[mt][2]), a3 = hu(tg[mt][3]);
            #pragma unroll
            for (int nt = 0; nt < 4; nt++)
                mma_f16(acc[mt][nt], a0, a1, a2, a3, b[nt][0], b[nt][1]);
        }
    };

    // ---- prologue: chunk 0 in flight ----
    loadX(0, 0);
    loadB(0, 0);
    asm volatile("cp.async.commit_group;" ::: "memory");

    // ---- main loop: distance-1, one barrier per chunk ----
    #pragma unroll 1
    for (int it = 0; it <= NIT; it++) {
        const int nc = it + 1;
        if (nc < NIT)        { loadX(nc, nc % 3); loadB(nc, nc % 3); }
        else if (nc == NIT)  { loadB_bias(nc % 3); }
        asm volatile("cp.async.commit_group;" ::: "memory");
        if (nc <= NIT) asm volatile("cp.async.wait_group 1;" ::: "memory");
        else           asm volatile("cp.async.wait_group 0;" ::: "memory");
        __syncthreads();
        if (it < NIT) compute(it % 3);
        else          compute_bias(it % 3);
    }

    // ---- epilogue: fragment store, 8B quad-coalesced ----
    #pragma unroll
    for (int mt = 0; mt < 4; mt++) {
        int m0 = m_blk + warpM * 64 + mt * 16 + (lane >> 2);
        #pragma unroll
        for (int nt = 0; nt < 4; nt++) {
            int n = n_blk + warpN * 32 + nt * 8 + 2 * (lane & 3);
            *(float2*)(out + (size_t)m0 * OUTF + n)       = make_float2(acc[mt][nt][0], acc[mt][nt][1]);
            *(float2*)(out + (size_t)(m0 + 8) * OUTF + n) = make_float2(acc[mt][nt][2], acc[mt][nt][3]);
        }
    }
}

// ---------------------------------------------------------------------------
extern "C" void kernel_launch(void* const* d_in, const int* in_sizes, int n_in,
                              void* d_out, int out_size) {
    const float* x  = (const float*)d_in[0];
    const float* gw = (const float*)d_in[1];
    const float* gb = (const float*)d_in[2];
    const float* pw = (const float*)d_in[3];
    const float* pb = (const float*)d_in[4];
    float* out = (float*)d_out;

    cudaFuncSetAttribute(gating_kernel, cudaFuncAttributeMaxDynamicSharedMemorySize,
                         INF * 17 * 4);
    cudaFuncSetAttribute(moe_mma_kernel, cudaFuncAttributeMaxDynamicSharedMemorySize,
                         SMEM_TOTAL);

    gating_kernel<<<BATCH / 32, 256, INF * 17 * 4>>>(x, gw, gb);
    conv_kernel<<<(unsigned)(NPW_BLOCKS + NX_BLOCKS + (OUTF * NL) / 8 / 256), 256>>>(pw, x, pb);

    dim3 grid(OUTF / BN, BATCH / BM);   // (8, 32) = 256 CTAs, 2/SM, one wave
    moe_mma_kernel<<<grid, 256, SMEM_TOTAL>>>(out);
}